// round 1
// baseline (speedup 1.0000x reference)
#include <cuda_runtime.h>
#include <cuda_bf16.h>
#include <stdint.h>

#define Bq 2048
#define Mm 8192
#define Dd 2048

// ---------------- scratch (device globals, no allocation) ----------------
__device__ __align__(16) float g_sims[(size_t)Bq * Mm];          // 64 MB
__device__ __align__(16) float g_qn[(size_t)Bq * Dd];            // 16 MB
__device__ __align__(16) float g_sn[(size_t)Mm * Dd];            // 64 MB
__device__ __align__(16) __nv_bfloat16 g_qnb[(size_t)Bq * Dd];   // 8 MB
__device__ __align__(16) __nv_bfloat16 g_snb[(size_t)Mm * Dd];   // 32 MB

__device__ __forceinline__ float warp_sum(float v) {
#pragma unroll
    for (int o = 16; o; o >>= 1) v += __shfl_xor_sync(0xffffffffu, v, o);
    return v;
}

// ---------------- kernel 1: row normalize + bf16 copy ----------------
__device__ __forceinline__ void normalize_row(const float* __restrict__ r,
                                              float* __restrict__ df,
                                              __nv_bfloat16* __restrict__ db) {
    float ss = 0.f;
    for (int i = threadIdx.x; i < Dd; i += 256) { float v = r[i]; ss = fmaf(v, v, ss); }
    __shared__ float red[8];
    int lane = threadIdx.x & 31, w = threadIdx.x >> 5;
    ss = warp_sum(ss);
    if (lane == 0) red[w] = ss;
    __syncthreads();
    if (w == 0) {
        float t = (lane < 8) ? red[lane] : 0.f;
        t = warp_sum(t);
        if (lane == 0) red[0] = 1.0f / fmaxf(sqrtf(t), 1e-8f);
    }
    __syncthreads();
    float inv = red[0];
    for (int i = threadIdx.x; i < Dd; i += 256) {
        float v = r[i] * inv;
        df[i] = v;
        db[i] = __float2bfloat16(v);
    }
}

__global__ __launch_bounds__(256) void normalize_q(const float* __restrict__ src) {
    size_t off = (size_t)blockIdx.x * Dd;
    normalize_row(src + off, g_qn + off, g_qnb + off);
}
__global__ __launch_bounds__(256) void normalize_s(const float* __restrict__ src) {
    size_t off = (size_t)blockIdx.x * Dd;
    normalize_row(src + off, g_sn + off, g_snb + off);
}

// ---------------- kernel 2: bf16 mma.sync GEMM: sims = qnb @ snb^T ----------------
#define BM 128
#define BN 128
#define BK 32
#define LDS_ (BK + 8)   // bf16 stride 40 (80B) -> conflict-free frag loads

__device__ __forceinline__ void mma_bf16(float d[4], const uint32_t a[4], const uint32_t b[2]) {
    asm volatile(
        "mma.sync.aligned.m16n8k16.row.col.f32.bf16.bf16.f32 "
        "{%0,%1,%2,%3}, {%4,%5,%6,%7}, {%8,%9}, {%0,%1,%2,%3};\n"
        : "+f"(d[0]), "+f"(d[1]), "+f"(d[2]), "+f"(d[3])
        : "r"(a[0]), "r"(a[1]), "r"(a[2]), "r"(a[3]), "r"(b[0]), "r"(b[1]));
}

__global__ __launch_bounds__(256, 1) void sims_gemm() {
    __shared__ __align__(16) __nv_bfloat16 As[BM * LDS_];
    __shared__ __align__(16) __nv_bfloat16 Bs[BN * LDS_];
    const int tid = threadIdx.x;
    const int lane = tid & 31;
    const int wid = tid >> 5;
    const int wm = wid >> 2;   // 0..1 -> 64 rows each
    const int wn = wid & 3;    // 0..3 -> 32 cols each
    const int g = lane >> 2, tk = lane & 3;
    const int bm0 = blockIdx.y * BM;
    const int bn0 = blockIdx.x * BN;

    const int lr0 = tid >> 2;          // 0..63
    const int ls0 = (tid & 3) * 8;     // 0/8/16/24 bf16 within k-tile

    const __nv_bfloat16* gA = g_qnb + (size_t)(bm0 + lr0) * Dd + ls0;
    const __nv_bfloat16* gB = g_snb + (size_t)(bn0 + lr0) * Dd + ls0;

    float acc[4][4][4];
#pragma unroll
    for (int mi = 0; mi < 4; mi++)
#pragma unroll
        for (int ni = 0; ni < 4; ni++)
#pragma unroll
            for (int k = 0; k < 4; k++) acc[mi][ni][k] = 0.f;

    uint4 ra0, ra1, rb0, rb1;
    ra0 = *(const uint4*)(gA);
    ra1 = *(const uint4*)(gA + (size_t)64 * Dd);
    rb0 = *(const uint4*)(gB);
    rb1 = *(const uint4*)(gB + (size_t)64 * Dd);

    __nv_bfloat16* sA0 = &As[lr0 * LDS_ + ls0];
    __nv_bfloat16* sA1 = &As[(lr0 + 64) * LDS_ + ls0];
    __nv_bfloat16* sB0 = &Bs[lr0 * LDS_ + ls0];
    __nv_bfloat16* sB1 = &Bs[(lr0 + 64) * LDS_ + ls0];

    *(uint4*)sA0 = ra0; *(uint4*)sA1 = ra1;
    *(uint4*)sB0 = rb0; *(uint4*)sB1 = rb1;
    __syncthreads();

    const int NT = Dd / BK;   // 64
    for (int kt = 0; kt < NT; kt++) {
        if (kt + 1 < NT) {
            const __nv_bfloat16* pA = gA + (size_t)(kt + 1) * BK;
            const __nv_bfloat16* pB = gB + (size_t)(kt + 1) * BK;
            ra0 = *(const uint4*)(pA);
            ra1 = *(const uint4*)(pA + (size_t)64 * Dd);
            rb0 = *(const uint4*)(pB);
            rb1 = *(const uint4*)(pB + (size_t)64 * Dd);
        }
#pragma unroll
        for (int ks = 0; ks < 2; ks++) {
            const int kb = ks * 16 + tk * 2;
            uint32_t af[4][4], bf[4][2];
#pragma unroll
            for (int mi = 0; mi < 4; mi++) {
                int r0 = (wm * 64 + mi * 16 + g) * LDS_;
                af[mi][0] = *(const uint32_t*)(&As[r0 + kb]);
                af[mi][1] = *(const uint32_t*)(&As[r0 + 8 * LDS_ + kb]);
                af[mi][2] = *(const uint32_t*)(&As[r0 + kb + 8]);
                af[mi][3] = *(const uint32_t*)(&As[r0 + 8 * LDS_ + kb + 8]);
            }
#pragma unroll
            for (int ni = 0; ni < 4; ni++) {
                int c0 = (wn * 32 + ni * 8 + g) * LDS_;
                bf[ni][0] = *(const uint32_t*)(&Bs[c0 + kb]);
                bf[ni][1] = *(const uint32_t*)(&Bs[c0 + kb + 8]);
            }
#pragma unroll
            for (int mi = 0; mi < 4; mi++)
#pragma unroll
                for (int ni = 0; ni < 4; ni++)
                    mma_bf16(acc[mi][ni], af[mi], bf[ni]);
        }
        __syncthreads();
        if (kt + 1 < NT) {
            *(uint4*)sA0 = ra0; *(uint4*)sA1 = ra1;
            *(uint4*)sB0 = rb0; *(uint4*)sB1 = rb1;
            __syncthreads();
        }
    }

#pragma unroll
    for (int mi = 0; mi < 4; mi++) {
        int row = bm0 + wm * 64 + mi * 16 + g;
#pragma unroll
        for (int ni = 0; ni < 4; ni++) {
            int col = bn0 + wn * 32 + ni * 8 + tk * 2;
            *(float2*)(&g_sims[(size_t)row * Mm + col]) =
                make_float2(acc[mi][ni][0], acc[mi][ni][1]);
            *(float2*)(&g_sims[(size_t)(row + 8) * Mm + col]) =
                make_float2(acc[mi][ni][2], acc[mi][ni][3]);
        }
    }
}

// ---------------- kernel 3: stats + softmax gather + fallbacks ----------------
#define CAP 256

__global__ __launch_bounds__(256) void stats_kernel(const float* __restrict__ tgt,
                                                    float* __restrict__ out) {
    const int b = blockIdx.x;
    __shared__ float srow[Mm];        // 32 KB: sims row
    __shared__ float qrow[Dd];        // 8 KB : qn row
    __shared__ int   cidx[CAP];
    __shared__ float cex[CAP];
    __shared__ float cw[CAP];
    __shared__ float redf[8];
    __shared__ float tbv[256];
    __shared__ int   tbi[256];
    __shared__ int s_ncand, s_cnt, s_fcnt, s_am, s_nfin;
    __shared__ float s_mean;

    const int tid = threadIdx.x, lane = tid & 31, w = tid >> 5;
    const float* simrow = g_sims + (size_t)b * Mm;
    for (int i = tid; i < Mm; i += 256) srow[i] = simrow[i];
    for (int i = tid; i < Dd; i += 256) qrow[i] = g_qn[(size_t)b * Dd + i];
    __syncthreads();

    // ordered (ascending index, deterministic) candidate collection by warp 0
    if (w == 0) {
        int cnt = 0;
        for (int base = 0; base < Mm; base += 32) {
            float v = srow[base + lane];
            unsigned bal = __ballot_sync(0xffffffffu, v > 0.49f);
            if (v > 0.49f) {
                int p = cnt + __popc(bal & ((1u << lane) - 1u));
                if (p < CAP) cidx[p] = base + lane;
            }
            cnt += __popc(bal);
        }
        if (lane == 0) s_ncand = (cnt < CAP) ? cnt : CAP;
    }
    __syncthreads();
    const int nc = s_ncand;

    // exact fp32 recompute of candidate sims (block-cooperative dot)
    for (int c = 0; c < nc; c++) {
        const float* srn = g_sn + (size_t)cidx[c] * Dd;
        float p = 0.f;
        for (int i = tid; i < Dd; i += 256) p = fmaf(qrow[i], srn[i], p);
        p = warp_sum(p);
        if (lane == 0) redf[w] = p;
        __syncthreads();
        if (tid == 0) {
            float t = 0.f;
            for (int j = 0; j < 8; j++) t += redf[j];
            cex[c] = t;
            srow[cidx[c]] = t;   // make argmin fallback use exact values too
        }
        __syncthreads();
    }

    if (tid == 0) {
        int cnt = 0; float sum = 0.f;
        for (int c = 0; c < nc; c++) if (cex[c] > 0.5f) { cnt++; sum += cex[c]; }
        float fc = (float)(cnt > 0 ? cnt : 1);
        float mean = sum / fc;
        float var = 0.f;
        for (int c = 0; c < nc; c++) if (cex[c] > 0.5f) { float d = cex[c] - mean; var = fmaf(d, d, var); }
        var /= fc;
        float dyn = mean - 0.5f * sqrtf(var);
        float mx = -1e30f; int fcnt = 0;
        for (int c = 0; c < nc; c++)
            if (cex[c] > 0.5f && cex[c] > dyn) { fcnt++; if (cex[c] > mx) mx = cex[c]; }
        int nf = 0;
        if (fcnt > 0) {
            float den = 0.f;
            for (int c = 0; c < nc; c++) {
                if (cex[c] > 0.5f && cex[c] > dyn) { float e = expf(cex[c] - mx); cw[c] = e; den += e; }
                else cw[c] = 0.f;
            }
            float inv = 1.0f / den;
            for (int c = 0; c < nc; c++)
                if (cw[c] > 0.f) { cidx[nf] = cidx[c]; cw[nf] = cw[c] * inv; nf++; }
        }
        s_cnt = cnt; s_fcnt = fcnt; s_mean = mean; s_nfin = nf;
    }
    __syncthreads();

    float* orow = out + (size_t)b * Dd;

    if (s_cnt == 0) {                       // fallback 2: zeros
        for (int i = tid; i < Dd; i += 256) orow[i] = 0.f;
        return;
    }
    if (s_fcnt == 0) {                      // fallback 1: target at argmin |sim - mean|
        float bv = 3.4e38f; int bi = 0x7fffffff;
        const float mean = s_mean;
        for (int i = tid; i < Mm; i += 256) {
            float v = fabsf(srow[i] - mean);
            if (v < bv) { bv = v; bi = i; }
        }
        tbv[tid] = bv; tbi[tid] = bi;
        __syncthreads();
        if (tid == 0) {
            float best = tbv[0]; int besti = tbi[0];
            for (int t = 1; t < 256; t++) {
                if (tbv[t] < best || (tbv[t] == best && tbi[t] < besti)) { best = tbv[t]; besti = tbi[t]; }
            }
            s_am = besti;
        }
        __syncthreads();
        const float* trow = tgt + (size_t)s_am * Dd;
        for (int i = tid; i < Dd; i += 256) orow[i] = trow[i];
        return;
    }

    const int nf = s_nfin;                  // softmax-weighted gather
    for (int i = tid; i < Dd; i += 256) {
        float acc = 0.f;
        for (int c = 0; c < nf; c++)
            acc = fmaf(cw[c], tgt[(size_t)cidx[c] * Dd + i], acc);
        orow[i] = acc;
    }
}

// ---------------- launch ----------------
extern "C" void kernel_launch(void* const* d_in, const int* in_sizes, int n_in,
                              void* d_out, int out_size) {
    const float* query      = (const float*)d_in[0];
    const float* query_set  = (const float*)d_in[1];
    const float* target_set = (const float*)d_in[2];
    float* out = (float*)d_out;

    normalize_q<<<Bq, 256>>>(query);
    normalize_s<<<Mm, 256>>>(query_set);
    dim3 grid(Mm / BN, Bq / BM);
    sims_gemm<<<grid, 256>>>();
    stats_kernel<<<Bq, 256>>>(target_set, out);
}

// round 5
// speedup vs baseline: 1.3495x; 1.3495x over previous
#include <cuda_runtime.h>
#include <cuda_bf16.h>
#include <stdint.h>

#define Bq 2048
#define Mm 8192
#define Dd 2048
#define CAP 512

// ---- GEMM tiling ----
#define BM 128
#define BN 128
#define BK 64
#define NT (Dd / BK)              // 32
#define LDS_ 72                   // padded stride (elems): conflict-free frag reads
#define ABUF (BM * LDS_)
#define BBUF (BN * LDS_)
#define DYN_SMEM ((2 * ABUF + 2 * BBUF) * 2)   // 73728 bytes

// ---------------- scratch (device globals, no allocation) ----------------
__device__ __align__(16) __nv_bfloat16 g_qnb[(size_t)Bq * Dd];   // 8 MB
__device__ __align__(16) __nv_bfloat16 g_snb[(size_t)Mm * Dd];   // 32 MB
__device__ float g_qinv[Bq];
__device__ float g_sinv[Mm];
__device__ int   g_cnt[Bq];
__device__ int   g_cand[(size_t)Bq * CAP];

__device__ __forceinline__ float warp_sum(float v) {
#pragma unroll
    for (int o = 16; o; o >>= 1) v += __shfl_xor_sync(0xffffffffu, v, o);
    return v;
}

__device__ __forceinline__ void mma_bf16(float* d, const uint32_t* a, const uint32_t* b) {
    asm volatile(
        "mma.sync.aligned.m16n8k16.row.col.f32.bf16.bf16.f32 "
        "{%0,%1,%2,%3}, {%4,%5,%6,%7}, {%8,%9}, {%0,%1,%2,%3};\n"
        : "+f"(d[0]), "+f"(d[1]), "+f"(d[2]), "+f"(d[3])
        : "r"(a[0]), "r"(a[1]), "r"(a[2]), "r"(a[3]), "r"(b[0]), "r"(b[1]));
}

// ---------------- kernel 1: row norms + bf16 normalized copy ----------------
// NOTE: device globals are referenced INSIDE device code only (host cannot take
// their address as a kernel argument — that was the round-3/4 bug).
__device__ __forceinline__ void normalize_row_impl(const float* __restrict__ r,
                                                   __nv_bfloat16* __restrict__ db,
                                                   float* __restrict__ dinv_slot) {
    float ss = 0.f;
    for (int i = threadIdx.x; i < Dd; i += 256) { float v = r[i]; ss = fmaf(v, v, ss); }
    __shared__ float red[8];
    int lane = threadIdx.x & 31, w = threadIdx.x >> 5;
    ss = warp_sum(ss);
    if (lane == 0) red[w] = ss;
    __syncthreads();
    if (w == 0) {
        float t = (lane < 8) ? red[lane] : 0.f;
        t = warp_sum(t);
        if (lane == 0) red[0] = 1.0f / fmaxf(sqrtf(t), 1e-8f);
    }
    __syncthreads();
    const float inv = red[0];
    if (threadIdx.x == 0) *dinv_slot = inv;
    for (int i = threadIdx.x; i < Dd; i += 256) db[i] = __float2bfloat16(r[i] * inv);
}

__global__ __launch_bounds__(256) void normalize_q(const float* __restrict__ src) {
    const size_t off = (size_t)blockIdx.x * Dd;
    if (threadIdx.x == 0) g_cnt[blockIdx.x] = 0;    // reset per launch (grid == Bq)
    normalize_row_impl(src + off, g_qnb + off, &g_qinv[blockIdx.x]);
}
__global__ __launch_bounds__(256) void normalize_s(const float* __restrict__ src) {
    const size_t off = (size_t)blockIdx.x * Dd;
    normalize_row_impl(src + off, g_snb + off, &g_sinv[blockIdx.x]);
}

// ---------------- kernel 2: mma.sync GEMM, 2-stage smem, 1 sync/tile ----------------
__global__ __launch_bounds__(256, 1) void sims_gemm() {
    extern __shared__ __nv_bfloat16 sm[];
    __nv_bfloat16* Abuf = sm;              // [2][ABUF]
    __nv_bfloat16* Bbuf = sm + 2 * ABUF;   // [2][BBUF]

    const int tid = threadIdx.x;
    const int lane = tid & 31;
    const int wid = tid >> 5;
    const int wm = wid >> 2;     // 0..1 -> 64-row half
    const int wn = wid & 3;      // 0..3 -> 32-col quarter
    const int g = lane >> 2, tk = lane & 3;
    const int bm0 = blockIdx.y * BM;
    const int bn0 = blockIdx.x * BN;

    // global->smem fill: thread handles rows r+32i (i=0..3), elems [j*8, j*8+8)
    const int j = tid & 7;
    const int r = tid >> 3;
    const __nv_bfloat16* gA = g_qnb + (size_t)(bm0 + r) * Dd + j * 8;
    const __nv_bfloat16* gB = g_snb + (size_t)(bn0 + r) * Dd + j * 8;
    const int wofs = r * LDS_ + j * 8;

    float acc[4][4][4];
#pragma unroll
    for (int mi = 0; mi < 4; mi++)
#pragma unroll
        for (int ni = 0; ni < 4; ni++)
#pragma unroll
            for (int k = 0; k < 4; k++) acc[mi][ni][k] = 0.f;

    uint4 pa[4], pb[4];

#define LOADT(kt_) do {                                                        \
    const __nv_bfloat16* ak_ = gA + (size_t)(kt_) * BK;                        \
    const __nv_bfloat16* bk_ = gB + (size_t)(kt_) * BK;                        \
    _Pragma("unroll")                                                          \
    for (int i_ = 0; i_ < 4; i_++) {                                           \
        pa[i_] = *(const uint4*)(ak_ + (size_t)(32 * i_) * Dd);                \
        pb[i_] = *(const uint4*)(bk_ + (size_t)(32 * i_) * Dd);                \
    } } while (0)

#define STORET(s_) do {                                                        \
    __nv_bfloat16* as_ = Abuf + (s_) * ABUF + wofs;                            \
    __nv_bfloat16* bs_ = Bbuf + (s_) * BBUF + wofs;                            \
    _Pragma("unroll")                                                          \
    for (int i_ = 0; i_ < 4; i_++) {                                           \
        *(uint4*)(as_ + 32 * i_ * LDS_) = pa[i_];                              \
        *(uint4*)(bs_ + 32 * i_ * LDS_) = pb[i_];                              \
    } } while (0)

    LOADT(0);
    STORET(0);
    LOADT(1);

    for (int kt = 0; kt < NT; kt++) {
        __syncthreads();
        // store tile kt+1 into buf (kt+1)&1: its previous readers (tile kt-1)
        // finished before the barrier above. regs were loaded last iteration.
        if (kt + 1 < NT) STORET((kt + 1) & 1);
        if (kt + 2 < NT) LOADT(kt + 2);

        // compute tile kt from buf kt&1 (stored last iteration, pre-barrier)
        const __nv_bfloat16* As = Abuf + (kt & 1) * ABUF;
        const __nv_bfloat16* Bs = Bbuf + (kt & 1) * BBUF;
#pragma unroll
        for (int ks = 0; ks < 4; ks++) {
            const int kb = ks * 16 + tk * 2;
            uint32_t af[4][4], bf[4][2];
#pragma unroll
            for (int mi = 0; mi < 4; mi++) {
                const int r0 = (wm * 64 + mi * 16 + g) * LDS_;
                af[mi][0] = *(const uint32_t*)(&As[r0 + kb]);
                af[mi][1] = *(const uint32_t*)(&As[r0 + 8 * LDS_ + kb]);
                af[mi][2] = *(const uint32_t*)(&As[r0 + kb + 8]);
                af[mi][3] = *(const uint32_t*)(&As[r0 + 8 * LDS_ + kb + 8]);
            }
#pragma unroll
            for (int ni = 0; ni < 4; ni++) {
                const int c0 = (wn * 32 + ni * 8 + g) * LDS_;
                bf[ni][0] = *(const uint32_t*)(&Bs[c0 + kb]);
                bf[ni][1] = *(const uint32_t*)(&Bs[c0 + kb + 8]);
            }
#pragma unroll
            for (int mi = 0; mi < 4; mi++)
#pragma unroll
                for (int ni = 0; ni < 4; ni++)
                    mma_bf16(acc[mi][ni], af[mi], bf[ni]);
        }
    }

    // ---- epilogue: candidate push straight from registers ----
#pragma unroll
    for (int mi = 0; mi < 4; mi++) {
#pragma unroll
        for (int ni = 0; ni < 4; ni++) {
#pragma unroll
            for (int k = 0; k < 4; k++) {
                const float v = acc[mi][ni][k];
                if (v > 0.49f) {
                    const int row = bm0 + wm * 64 + mi * 16 + g + (k >> 1) * 8;
                    const int col = bn0 + wn * 32 + ni * 8 + tk * 2 + (k & 1);
                    const int pos = atomicAdd(&g_cnt[row], 1);
                    if (pos < CAP) g_cand[(size_t)row * CAP + pos] = col;
                }
            }
        }
    }
}

// ---------------- kernel 3: exact stats + softmax gather ----------------
__global__ __launch_bounds__(256) void stats2(const float* __restrict__ query,
                                              const float* __restrict__ qset,
                                              const float* __restrict__ tgt,
                                              float* __restrict__ out) {
    const int b = blockIdx.x;
    const int tid = threadIdx.x, lane = tid & 31, w = tid >> 5;
    float* orow = out + (size_t)b * Dd;

    const int nc = min(g_cnt[b], CAP);
    if (nc == 0) {
        for (int i = tid; i < Dd; i += 256) orow[i] = 0.f;
        return;
    }

    __shared__ float qrow[Dd];
    __shared__ int   cidx[CAP];
    __shared__ float cex[CAP];
    __shared__ float cw[CAP];
    __shared__ int s_state, s_am, s_nf;

    for (int i = tid; i < Dd; i += 256) qrow[i] = query[(size_t)b * Dd + i];
    for (int i = tid; i < nc; i += 256) cidx[i] = g_cand[(size_t)b * CAP + i];
    __syncthreads();

    if (tid == 0) {          // sort ascending for determinism (nc is tiny)
        for (int i = 1; i < nc; i++) {
            int key = cidx[i], k2 = i - 1;
            while (k2 >= 0 && cidx[k2] > key) { cidx[k2 + 1] = cidx[k2]; k2--; }
            cidx[k2 + 1] = key;
        }
    }
    __syncthreads();

    const float qinv = g_qinv[b];
    for (int c = w; c < nc; c += 8) {     // one warp per candidate: exact fp32 dot
        const float* srn = qset + (size_t)cidx[c] * Dd;
        float p = 0.f;
        for (int i = lane; i < Dd; i += 32) p = fmaf(qrow[i], srn[i], p);
        p = warp_sum(p);
        if (lane == 0) cex[c] = p * qinv * g_sinv[cidx[c]];
    }
    __syncthreads();

    if (tid == 0) {
        int cntE = 0; float sum = 0.f;
        for (int c = 0; c < nc; c++) if (cex[c] > 0.5f) { cntE++; sum += cex[c]; }
        if (cntE == 0) { s_state = 0; }
        else {
            const float fc = (float)cntE;
            const float mean = sum / fc;
            float var = 0.f;
            for (int c = 0; c < nc; c++)
                if (cex[c] > 0.5f) { float d = cex[c] - mean; var = fmaf(d, d, var); }
            var /= fc;
            const float dyn = mean - 0.5f * sqrtf(var);
            int fcnt = 0; float mx = -1e30f;
            for (int c = 0; c < nc; c++)
                if (cex[c] > 0.5f && cex[c] > dyn) { fcnt++; if (cex[c] > mx) mx = cex[c]; }
            if (fcnt == 0) {   // fallback 1: argmin |sim-mean| is provably a candidate
                float bv = 3.4e38f; int bi = 0;
                for (int c = 0; c < nc; c++) {
                    float dv = fabsf(cex[c] - mean);
                    if (dv < bv) { bv = dv; bi = cidx[c]; }
                }
                s_state = 1; s_am = bi;
            } else {
                float den = 0.f;
                for (int c = 0; c < nc; c++) {
                    if (cex[c] > 0.5f && cex[c] > dyn) { float e = __expf(cex[c] - mx); cw[c] = e; den += e; }
                    else cw[c] = 0.f;
                }
                const float inv = 1.0f / den;
                int nf = 0;
                for (int c = 0; c < nc; c++)
                    if (cw[c] > 0.f) { cidx[nf] = cidx[c]; cw[nf] = cw[c] * inv; nf++; }
                s_state = 2; s_nf = nf;
            }
        }
    }
    __syncthreads();

    if (s_state == 0) {
        for (int i = tid; i < Dd; i += 256) orow[i] = 0.f;
    } else if (s_state == 1) {
        const float* trow = tgt + (size_t)s_am * Dd;
        for (int i = tid; i < Dd; i += 256) orow[i] = trow[i];
    } else {
        const int nf = s_nf;
        for (int i = tid; i < Dd; i += 256) {
            float acc = 0.f;
            for (int c = 0; c < nf; c++)
                acc = fmaf(cw[c], tgt[(size_t)cidx[c] * Dd + i], acc);
            orow[i] = acc;
        }
    }
}

// ---------------- launch (only harness pointers cross the host/device line) ----
extern "C" void kernel_launch(void* const* d_in, const int* in_sizes, int n_in,
                              void* d_out, int out_size) {
    const float* query      = (const float*)d_in[0];
    const float* query_set  = (const float*)d_in[1];
    const float* target_set = (const float*)d_in[2];
    float* out = (float*)d_out;

    normalize_q<<<Bq, 256>>>(query);
    normalize_s<<<Mm, 256>>>(query_set);

    cudaFuncSetAttribute(sims_gemm, cudaFuncAttributeMaxDynamicSharedMemorySize, DYN_SMEM);
    dim3 grid(Mm / BN, Bq / BM);
    sims_gemm<<<grid, 256, DYN_SMEM>>>();

    stats2<<<Bq, 256>>>(query, query_set, target_set, out);
}

// round 6
// speedup vs baseline: 1.7999x; 1.3338x over previous
#include <cuda_runtime.h>
#include <cuda_bf16.h>
#include <stdint.h>

#define Bq 2048
#define Mm 8192
#define Dd 2048
#define CAP 512

// ---- GEMM tiling ----
#define BM 128
#define BN 128
#define BK 64                          // bf16 elems; 128 B per row
#define NTK (Dd / BK)                  // 32
#define A_SZ (BM * 128)                // bytes per stage
#define B_SZ (BN * 128)
#define STAGE (A_SZ + B_SZ)            // 32768
#define NSTAGE 4
#define DYN_SMEM (NSTAGE * STAGE + 1024)

// ---------------- scratch (device globals, referenced in device code ONLY) ----
__device__ __align__(16) __nv_bfloat16 g_qnb[(size_t)Bq * Dd];   // 8 MB
__device__ __align__(16) __nv_bfloat16 g_snb[(size_t)Mm * Dd];   // 32 MB
__device__ float g_qinv[Bq];
__device__ float g_sinv[Mm];
__device__ int   g_cnt[Bq];
__device__ int   g_cand[(size_t)Bq * CAP];

// ---------------- helpers ----------------
__device__ __forceinline__ uint32_t smem_u32(const void* p) {
    uint32_t a;
    asm("{ .reg .u64 t; cvta.to.shared.u64 t, %1; cvt.u32.u64 %0, t; }" : "=r"(a) : "l"(p));
    return a;
}
#define SW128(o) ((o) ^ (((o) >> 3) & 0x70))

__device__ __forceinline__ void cp_async16(uint32_t dst, const void* src) {
    asm volatile("cp.async.cg.shared.global [%0], [%1], 16;" :: "r"(dst), "l"(src) : "memory");
}
#define CP_COMMIT() asm volatile("cp.async.commit_group;" ::: "memory")
#define CP_WAIT(n)  asm volatile("cp.async.wait_group %0;" :: "n"(n) : "memory")

__device__ __forceinline__ void ldsm_x4(uint32_t* r, uint32_t addr) {
    asm volatile("ldmatrix.sync.aligned.m8n8.x4.shared.b16 {%0,%1,%2,%3}, [%4];"
                 : "=r"(r[0]), "=r"(r[1]), "=r"(r[2]), "=r"(r[3]) : "r"(addr));
}
__device__ __forceinline__ void mma_bf16(float* d, const uint32_t* a, const uint32_t* b) {
    asm volatile(
        "mma.sync.aligned.m16n8k16.row.col.f32.bf16.bf16.f32 "
        "{%0,%1,%2,%3}, {%4,%5,%6,%7}, {%8,%9}, {%0,%1,%2,%3};\n"
        : "+f"(d[0]), "+f"(d[1]), "+f"(d[2]), "+f"(d[3])
        : "r"(a[0]), "r"(a[1]), "r"(a[2]), "r"(a[3]), "r"(b[0]), "r"(b[1]));
}
__device__ __forceinline__ float warp_sum(float v) {
#pragma unroll
    for (int o = 16; o; o >>= 1) v += __shfl_xor_sync(0xffffffffu, v, o);
    return v;
}

// ---------------- kernel 1: merged row norms + bf16 normalized copy ----------------
__global__ __launch_bounds__(256) void normalize_all(const float* __restrict__ q,
                                                     const float* __restrict__ s) {
    const int b = blockIdx.x;
    const float* r;
    __nv_bfloat16* db;
    float* dinv_slot;
    if (b < Bq) {
        if (threadIdx.x == 0) g_cnt[b] = 0;    // reset per launch
        r = q + (size_t)b * Dd; db = g_qnb + (size_t)b * Dd; dinv_slot = &g_qinv[b];
    } else {
        const int m = b - Bq;
        r = s + (size_t)m * Dd; db = g_snb + (size_t)m * Dd; dinv_slot = &g_sinv[m];
    }
    float ss = 0.f;
    for (int i = threadIdx.x; i < Dd; i += 256) { float v = r[i]; ss = fmaf(v, v, ss); }
    __shared__ float red[8];
    int lane = threadIdx.x & 31, w = threadIdx.x >> 5;
    ss = warp_sum(ss);
    if (lane == 0) red[w] = ss;
    __syncthreads();
    if (w == 0) {
        float t = (lane < 8) ? red[lane] : 0.f;
        t = warp_sum(t);
        if (lane == 0) red[0] = 1.0f / fmaxf(sqrtf(t), 1e-8f);
    }
    __syncthreads();
    const float inv = red[0];
    if (threadIdx.x == 0) *dinv_slot = inv;
    for (int i = threadIdx.x; i < Dd; i += 256) db[i] = __float2bfloat16(r[i] * inv);
}

// ---------------- kernel 2: cp.async + ldmatrix + mma.sync GEMM ----------------
__global__ __launch_bounds__(256, 1) void sims_gemm() {
    extern __shared__ __align__(16) char dyn[];
    const int tid = threadIdx.x;
    const int lane = tid & 31;
    const int wid = tid >> 5;
    const int wm = wid >> 2;     // 0..1 : 64 rows
    const int wn = wid & 3;      // 0..3 : 32 cols

    // 1024-align dynamic smem
    const uint32_t draw = smem_u32(dyn);
    const uint32_t pad = (1024u - (draw & 1023u)) & 1023u;
    const uint32_t sm0 = draw + pad;

    const int bm0 = blockIdx.y * BM;
    const int bn0 = blockIdx.x * BN;

    // ---- cp.async fill mapping ----
    const int j = tid & 7;       // 16B chunk in 128B row
    const int r = tid >> 3;      // 0..31
    uint32_t sw[4];
#pragma unroll
    for (int i = 0; i < 4; i++) sw[i] = SW128((uint32_t)((r + 32 * i) * 128 + j * 16));
    const __nv_bfloat16* Ag = g_qnb + (size_t)(bm0 + r) * Dd + j * 8;
    const __nv_bfloat16* Bg = g_snb + (size_t)(bn0 + r) * Dd + j * 8;

    // ---- ldmatrix address precompute ----
    const int sub = lane & 7;
    const uint32_t xr = (uint32_t)sub << 4;
    const uint32_t offA = ((lane >> 4) & 1) * 16;       // k-half select
    const int rowA_off = ((lane >> 3) & 1) * 8 + sub;   // row +0/+8
    uint32_t aRow[4];
#pragma unroll
    for (int mi = 0; mi < 4; mi++)
        aRow[mi] = sm0 + (uint32_t)(wm * 64 + mi * 16 + rowA_off) * 128;
    const uint32_t offB = ((lane >> 3) & 1) * 16;
    const int rowB_off = ((lane >> 4) & 1) * 8 + sub;
    uint32_t bRow[2];
#pragma unroll
    for (int nj = 0; nj < 2; nj++)
        bRow[nj] = sm0 + A_SZ + (uint32_t)(wn * 32 + nj * 16 + rowB_off) * 128;

    float acc[4][4][4];
#pragma unroll
    for (int mi = 0; mi < 4; mi++)
#pragma unroll
        for (int ni = 0; ni < 4; ni++)
#pragma unroll
            for (int k = 0; k < 4; k++) acc[mi][ni][k] = 0.f;

    // ---- prologue: issue first NSTAGE-1 stages ----
#pragma unroll
    for (int s = 0; s < NSTAGE - 1; s++) {
        const uint32_t st = sm0 + s * STAGE;
        const __nv_bfloat16* ak = Ag + s * BK;
        const __nv_bfloat16* bk = Bg + s * BK;
#pragma unroll
        for (int i = 0; i < 4; i++) cp_async16(st + sw[i], ak + (size_t)(32 * i) * Dd);
#pragma unroll
        for (int i = 0; i < 4; i++) cp_async16(st + A_SZ + sw[i], bk + (size_t)(32 * i) * Dd);
        CP_COMMIT();
    }

    for (int kt = 0; kt < NTK; kt++) {
        CP_WAIT(NSTAGE - 2);      // this thread's stage-kt copies done
        __syncthreads();          // -> all threads' copies visible

        // issue stage kt+3 into slot (kt+3)&3 (its prior readers: tile kt-1, done)
        if (kt + NSTAGE - 1 < NTK) {
            const int s = (kt + NSTAGE - 1) & (NSTAGE - 1);
            const uint32_t st = sm0 + s * STAGE;
            const __nv_bfloat16* ak = Ag + (size_t)(kt + NSTAGE - 1) * BK;
            const __nv_bfloat16* bk = Bg + (size_t)(kt + NSTAGE - 1) * BK;
#pragma unroll
            for (int i = 0; i < 4; i++) cp_async16(st + sw[i], ak + (size_t)(32 * i) * Dd);
#pragma unroll
            for (int i = 0; i < 4; i++) cp_async16(st + A_SZ + sw[i], bk + (size_t)(32 * i) * Dd);
        }
        CP_COMMIT();

        // compute stage kt
        const uint32_t sbase = (uint32_t)((kt & (NSTAGE - 1)) * STAGE);
#pragma unroll
        for (int ks = 0; ks < 4; ks++) {
            const uint32_t kpA = (((uint32_t)ks * 32 + offA) ^ xr) + sbase;
            const uint32_t kpB = (((uint32_t)ks * 32 + offB) ^ xr) + sbase;
            uint32_t af[4][4], bfr[2][4];
#pragma unroll
            for (int mi = 0; mi < 4; mi++) ldsm_x4(af[mi], aRow[mi] + kpA);
#pragma unroll
            for (int nj = 0; nj < 2; nj++) ldsm_x4(bfr[nj], bRow[nj] + kpB);
#pragma unroll
            for (int mi = 0; mi < 4; mi++)
#pragma unroll
                for (int ni = 0; ni < 4; ni++)
                    mma_bf16(acc[mi][ni], af[mi], &bfr[ni >> 1][(ni & 1) * 2]);
        }
    }

    // ---- epilogue: candidate push straight from registers ----
    const int g = lane >> 2, tk = lane & 3;
#pragma unroll
    for (int mi = 0; mi < 4; mi++) {
#pragma unroll
        for (int ni = 0; ni < 4; ni++) {
#pragma unroll
            for (int k = 0; k < 4; k++) {
                const float v = acc[mi][ni][k];
                if (v > 0.49f) {
                    const int row = bm0 + wm * 64 + mi * 16 + g + (k >> 1) * 8;
                    const int col = bn0 + wn * 32 + ni * 8 + tk * 2 + (k & 1);
                    const int pos = atomicAdd(&g_cnt[row], 1);
                    if (pos < CAP) g_cand[(size_t)row * CAP + pos] = col;
                }
            }
        }
    }
}

// ---------------- kernel 3: exact stats + softmax gather (vectorized) ----------------
__global__ __launch_bounds__(256) void stats2(const float* __restrict__ query,
                                              const float* __restrict__ qset,
                                              const float* __restrict__ tgt,
                                              float* __restrict__ out) {
    const int b = blockIdx.x;
    const int tid = threadIdx.x, lane = tid & 31, w = tid >> 5;
    float* orow = out + (size_t)b * Dd;

    const int nc = min(g_cnt[b], CAP);
    if (nc == 0) {
        for (int i = tid; i < Dd; i += 256) orow[i] = 0.f;
        return;
    }

    __shared__ __align__(16) float qrow[Dd];
    __shared__ int   cidx[CAP];
    __shared__ float cex[CAP];
    __shared__ float cw[CAP];
    __shared__ int s_state, s_am, s_nf;

    {
        const float4* q4 = (const float4*)(query + (size_t)b * Dd);
        float4* d4 = (float4*)qrow;
        for (int i = tid; i < Dd / 4; i += 256) d4[i] = q4[i];
    }
    for (int i = tid; i < nc; i += 256) cidx[i] = g_cand[(size_t)b * CAP + i];
    __syncthreads();

    if (tid == 0) {          // sort ascending for determinism (nc is tiny)
        for (int i = 1; i < nc; i++) {
            int key = cidx[i], k2 = i - 1;
            while (k2 >= 0 && cidx[k2] > key) { cidx[k2 + 1] = cidx[k2]; k2--; }
            cidx[k2 + 1] = key;
        }
    }
    __syncthreads();

    const float qinv = g_qinv[b];
    const float4* q4 = (const float4*)qrow;
    for (int c = w; c < nc; c += 8) {     // one warp per candidate: exact fp32 dot
        const float4* s4 = (const float4*)(qset + (size_t)cidx[c] * Dd);
        float p = 0.f;
        for (int i = lane; i < Dd / 4; i += 32) {
            float4 a = q4[i], v = s4[i];
            p = fmaf(a.x, v.x, p); p = fmaf(a.y, v.y, p);
            p = fmaf(a.z, v.z, p); p = fmaf(a.w, v.w, p);
        }
        p = warp_sum(p);
        if (lane == 0) cex[c] = p * qinv * g_sinv[cidx[c]];
    }
    __syncthreads();

    if (tid == 0) {
        int cntE = 0; float sum = 0.f;
        for (int c = 0; c < nc; c++) if (cex[c] > 0.5f) { cntE++; sum += cex[c]; }
        if (cntE == 0) { s_state = 0; }
        else {
            const float fc = (float)cntE;
            const float mean = sum / fc;
            float var = 0.f;
            for (int c = 0; c < nc; c++)
                if (cex[c] > 0.5f) { float d = cex[c] - mean; var = fmaf(d, d, var); }
            var /= fc;
            const float dyn = mean - 0.5f * sqrtf(var);
            int fcnt = 0; float mx = -1e30f;
            for (int c = 0; c < nc; c++)
                if (cex[c] > 0.5f && cex[c] > dyn) { fcnt++; if (cex[c] > mx) mx = cex[c]; }
            if (fcnt == 0) {   // fallback 1: argmin |sim-mean| is provably a candidate
                float bv = 3.4e38f; int bi = 0;
                for (int c = 0; c < nc; c++) {
                    float dv = fabsf(cex[c] - mean);
                    if (dv < bv) { bv = dv; bi = cidx[c]; }
                }
                s_state = 1; s_am = bi;
            } else {
                float den = 0.f;
                for (int c = 0; c < nc; c++) {
                    if (cex[c] > 0.5f && cex[c] > dyn) { float e = __expf(cex[c] - mx); cw[c] = e; den += e; }
                    else cw[c] = 0.f;
                }
                const float inv = 1.0f / den;
                int nf = 0;
                for (int c = 0; c < nc; c++)
                    if (cw[c] > 0.f) { cidx[nf] = cidx[c]; cw[nf] = cw[c] * inv; nf++; }
                s_state = 2; s_nf = nf;
            }
        }
    }
    __syncthreads();

    float4* o4 = (float4*)orow;
    if (s_state == 0) {
        const float4 z = make_float4(0.f, 0.f, 0.f, 0.f);
        for (int i = tid; i < Dd / 4; i += 256) o4[i] = z;
    } else if (s_state == 1) {
        const float4* t4 = (const float4*)(tgt + (size_t)s_am * Dd);
        for (int i = tid; i < Dd / 4; i += 256) o4[i] = t4[i];
    } else {
        const int nf = s_nf;
        for (int i = tid; i < Dd / 4; i += 256) {
            float4 a = make_float4(0.f, 0.f, 0.f, 0.f);
            for (int c = 0; c < nf; c++) {
                const float4 t = *(const float4*)(tgt + (size_t)cidx[c] * Dd + i * 4);
                const float wgt = cw[c];
                a.x = fmaf(wgt, t.x, a.x); a.y = fmaf(wgt, t.y, a.y);
                a.z = fmaf(wgt, t.z, a.z); a.w = fmaf(wgt, t.w, a.w);
            }
            o4[i] = a;
        }
    }
}

// ---------------- launch (only harness pointers cross the host/device line) ----
extern "C" void kernel_launch(void* const* d_in, const int* in_sizes, int n_in,
                              void* d_out, int out_size) {
    const float* query      = (const float*)d_in[0];
    const float* query_set  = (const float*)d_in[1];
    const float* target_set = (const float*)d_in[2];
    float* out = (float*)d_out;

    normalize_all<<<Bq + Mm, 256>>>(query, query_set);

    cudaFuncSetAttribute(sims_gemm, cudaFuncAttributeMaxDynamicSharedMemorySize, DYN_SMEM);
    dim3 grid(Mm / BN, Bq / BM);
    sims_gemm<<<grid, 256, DYN_SMEM>>>();

    stats2<<<Bq, 256>>>(query, query_set, target_set, out);
}

// round 7
// speedup vs baseline: 2.0717x; 1.1510x over previous
#include <cuda_runtime.h>
#include <cuda_bf16.h>
#include <cuda_fp8.h>
#include <stdint.h>

#define Bq 2048
#define Mm 8192
#define Dd 2048
#define CAP 512

// ---- GEMM tiling (fp8: 128 elems per 128B k-row) ----
#define BM 128
#define BN 128
#define BKB 128                        // k-chunk in BYTES (= 128 fp8 elems)
#define NTK (Dd / BKB)                 // 16
#define A_SZ (BM * 128)                // bytes per stage
#define B_SZ (BN * 128)
#define STAGE (A_SZ + B_SZ)            // 32768
#define NSTAGE 4
#define DYN_SMEM (NSTAGE * STAGE + 1024)

// ---------------- scratch (device globals, referenced in device code ONLY) ----
__device__ __align__(16) uint8_t g_qn8[(size_t)Bq * Dd];   // 4 MB  (e4m3)
__device__ __align__(16) uint8_t g_sn8[(size_t)Mm * Dd];   // 16 MB (e4m3)
__device__ float g_qinv[Bq];
__device__ float g_sinv[Mm];
__device__ int   g_cnt[Bq];
__device__ int   g_cand[(size_t)Bq * CAP];

// ---------------- helpers ----------------
__device__ __forceinline__ uint32_t smem_u32(const void* p) {
    uint32_t a;
    asm("{ .reg .u64 t; cvta.to.shared.u64 t, %1; cvt.u32.u64 %0, t; }" : "=r"(a) : "l"(p));
    return a;
}
#define SW128(o) ((o) ^ (((o) >> 3) & 0x70))

__device__ __forceinline__ void cp_async16(uint32_t dst, const void* src) {
    asm volatile("cp.async.cg.shared.global [%0], [%1], 16;" :: "r"(dst), "l"(src) : "memory");
}
#define CP_COMMIT() asm volatile("cp.async.commit_group;" ::: "memory")
#define CP_WAIT(n)  asm volatile("cp.async.wait_group %0;" :: "n"(n) : "memory")

__device__ __forceinline__ void ldsm_x4(uint32_t* r, uint32_t addr) {
    asm volatile("ldmatrix.sync.aligned.m8n8.x4.shared.b16 {%0,%1,%2,%3}, [%4];"
                 : "=r"(r[0]), "=r"(r[1]), "=r"(r[2]), "=r"(r[3]) : "r"(addr));
}
// fp8 e4m3 MMA: fragment byte-layout identical to m16n8k16 bf16
__device__ __forceinline__ void mma_fp8(float* d, const uint32_t* a, const uint32_t* b) {
    asm volatile(
        "mma.sync.aligned.m16n8k32.row.col.f32.e4m3.e4m3.f32 "
        "{%0,%1,%2,%3}, {%4,%5,%6,%7}, {%8,%9}, {%0,%1,%2,%3};\n"
        : "+f"(d[0]), "+f"(d[1]), "+f"(d[2]), "+f"(d[3])
        : "r"(a[0]), "r"(a[1]), "r"(a[2]), "r"(a[3]), "r"(b[0]), "r"(b[1]));
}
__device__ __forceinline__ float warp_sum(float v) {
#pragma unroll
    for (int o = 16; o; o >>= 1) v += __shfl_xor_sync(0xffffffffu, v, o);
    return v;
}

// ---------------- kernel 1: merged row norms + e4m3 normalized copy ----------------
__global__ __launch_bounds__(256) void normalize_all(const float* __restrict__ q,
                                                     const float* __restrict__ s) {
    const int b = blockIdx.x;
    const float* r;
    uint8_t* db;
    float* dinv_slot;
    if (b < Bq) {
        if (threadIdx.x == 0) g_cnt[b] = 0;    // reset per launch
        r = q + (size_t)b * Dd; db = g_qn8 + (size_t)b * Dd; dinv_slot = &g_qinv[b];
    } else {
        const int m = b - Bq;
        r = s + (size_t)m * Dd; db = g_sn8 + (size_t)m * Dd; dinv_slot = &g_sinv[m];
    }
    const float4* r4 = (const float4*)r;
    float4 v[2];
    float ss = 0.f;
#pragma unroll
    for (int k = 0; k < 2; k++) {
        v[k] = r4[threadIdx.x + k * 256];
        ss = fmaf(v[k].x, v[k].x, ss); ss = fmaf(v[k].y, v[k].y, ss);
        ss = fmaf(v[k].z, v[k].z, ss); ss = fmaf(v[k].w, v[k].w, ss);
    }
    __shared__ float red[8];
    int lane = threadIdx.x & 31, w = threadIdx.x >> 5;
    ss = warp_sum(ss);
    if (lane == 0) red[w] = ss;
    __syncthreads();
    if (w == 0) {
        float t = (lane < 8) ? red[lane] : 0.f;
        t = warp_sum(t);
        if (lane == 0) red[0] = 1.0f / fmaxf(sqrtf(t), 1e-8f);
    }
    __syncthreads();
    const float inv = red[0];
    if (threadIdx.x == 0) *dinv_slot = inv;
    uint32_t* d32 = (uint32_t*)db;
#pragma unroll
    for (int k = 0; k < 2; k++) {
        float4 n = make_float4(v[k].x * inv, v[k].y * inv, v[k].z * inv, v[k].w * inv);
        __nv_fp8x4_e4m3 p(n);
        d32[threadIdx.x + k * 256] = *(uint32_t*)&p;
    }
}

// ---------------- kernel 2: cp.async + ldmatrix + fp8 mma.sync GEMM ----------------
__global__ __launch_bounds__(256, 1) void sims_gemm() {
    extern __shared__ __align__(16) char dyn[];
    const int tid = threadIdx.x;
    const int lane = tid & 31;
    const int wid = tid >> 5;
    const int wm = wid >> 2;     // 0..1 : 64 rows
    const int wn = wid & 3;      // 0..3 : 32 cols

    // 1024-align dynamic smem
    const uint32_t draw = smem_u32(dyn);
    const uint32_t pad = (1024u - (draw & 1023u)) & 1023u;
    const uint32_t sm0 = draw + pad;

    const int bm0 = blockIdx.y * BM;
    const int bn0 = blockIdx.x * BN;

    // ---- cp.async fill mapping (byte-based) ----
    const int j = tid & 7;       // 16B chunk in 128B row
    const int r = tid >> 3;      // 0..31
    uint32_t sw[4];
#pragma unroll
    for (int i = 0; i < 4; i++) sw[i] = SW128((uint32_t)((r + 32 * i) * 128 + j * 16));
    const uint8_t* Ag = g_qn8 + (size_t)(bm0 + r) * Dd + j * 16;
    const uint8_t* Bg = g_sn8 + (size_t)(bn0 + r) * Dd + j * 16;

    // ---- ldmatrix address precompute (byte-identical to bf16 path) ----
    const int sub = lane & 7;
    const uint32_t xr = (uint32_t)sub << 4;
    const uint32_t offA = ((lane >> 4) & 1) * 16;       // k-half select (16B)
    const int rowA_off = ((lane >> 3) & 1) * 8 + sub;   // row +0/+8
    uint32_t aRow[4];
#pragma unroll
    for (int mi = 0; mi < 4; mi++)
        aRow[mi] = sm0 + (uint32_t)(wm * 64 + mi * 16 + rowA_off) * 128;
    const uint32_t offB = ((lane >> 3) & 1) * 16;
    const int rowB_off = ((lane >> 4) & 1) * 8 + sub;
    uint32_t bRow[2];
#pragma unroll
    for (int nj = 0; nj < 2; nj++)
        bRow[nj] = sm0 + A_SZ + (uint32_t)(wn * 32 + nj * 16 + rowB_off) * 128;

    float acc[4][4][4];
#pragma unroll
    for (int mi = 0; mi < 4; mi++)
#pragma unroll
        for (int ni = 0; ni < 4; ni++)
#pragma unroll
            for (int k = 0; k < 4; k++) acc[mi][ni][k] = 0.f;

    // ---- prologue: issue first NSTAGE-1 stages ----
#pragma unroll
    for (int s = 0; s < NSTAGE - 1; s++) {
        const uint32_t st = sm0 + s * STAGE;
        const uint8_t* ak = Ag + (size_t)s * BKB;
        const uint8_t* bk = Bg + (size_t)s * BKB;
#pragma unroll
        for (int i = 0; i < 4; i++) cp_async16(st + sw[i], ak + (size_t)(32 * i) * Dd);
#pragma unroll
        for (int i = 0; i < 4; i++) cp_async16(st + A_SZ + sw[i], bk + (size_t)(32 * i) * Dd);
        CP_COMMIT();
    }

    for (int kt = 0; kt < NTK; kt++) {
        CP_WAIT(NSTAGE - 2);      // this thread's stage-kt copies done
        __syncthreads();          // -> all threads' copies visible

        // issue stage kt+3 into slot (kt+3)&3 (its prior readers: tile kt-1, done)
        if (kt + NSTAGE - 1 < NTK) {
            const int s = (kt + NSTAGE - 1) & (NSTAGE - 1);
            const uint32_t st = sm0 + s * STAGE;
            const uint8_t* ak = Ag + (size_t)(kt + NSTAGE - 1) * BKB;
            const uint8_t* bk = Bg + (size_t)(kt + NSTAGE - 1) * BKB;
#pragma unroll
            for (int i = 0; i < 4; i++) cp_async16(st + sw[i], ak + (size_t)(32 * i) * Dd);
#pragma unroll
            for (int i = 0; i < 4; i++) cp_async16(st + A_SZ + sw[i], bk + (size_t)(32 * i) * Dd);
        }
        CP_COMMIT();

        // compute stage kt: 4 ks-steps of 32 k-bytes (k32 fp8 each)
        const uint32_t sbase = (uint32_t)((kt & (NSTAGE - 1)) * STAGE);
#pragma unroll
        for (int ks = 0; ks < 4; ks++) {
            const uint32_t kpA = (((uint32_t)ks * 32 + offA) ^ xr) + sbase;
            const uint32_t kpB = (((uint32_t)ks * 32 + offB) ^ xr) + sbase;
            uint32_t af[4][4], bfr[2][4];
#pragma unroll
            for (int mi = 0; mi < 4; mi++) ldsm_x4(af[mi], aRow[mi] + kpA);
#pragma unroll
            for (int nj = 0; nj < 2; nj++) ldsm_x4(bfr[nj], bRow[nj] + kpB);
#pragma unroll
            for (int mi = 0; mi < 4; mi++)
#pragma unroll
                for (int ni = 0; ni < 4; ni++)
                    mma_fp8(acc[mi][ni], af[mi], &bfr[ni >> 1][(ni & 1) * 2]);
        }
    }

    // ---- epilogue: candidate push straight from registers ----
    const int g = lane >> 2, tk = lane & 3;
#pragma unroll
    for (int mi = 0; mi < 4; mi++) {
#pragma unroll
        for (int ni = 0; ni < 4; ni++) {
#pragma unroll
            for (int k = 0; k < 4; k++) {
                const float v = acc[mi][ni][k];
                if (v > 0.45f) {
                    const int row = bm0 + wm * 64 + mi * 16 + g + (k >> 1) * 8;
                    const int col = bn0 + wn * 32 + ni * 8 + tk * 2 + (k & 1);
                    const int pos = atomicAdd(&g_cnt[row], 1);
                    if (pos < CAP) g_cand[(size_t)row * CAP + pos] = col;
                }
            }
        }
    }
}

// ---------------- kernel 3: exact stats + softmax gather (vectorized) ----------------
__global__ __launch_bounds__(256) void stats2(const float* __restrict__ query,
                                              const float* __restrict__ qset,
                                              const float* __restrict__ tgt,
                                              float* __restrict__ out) {
    const int b = blockIdx.x;
    const int tid = threadIdx.x, lane = tid & 31, w = tid >> 5;
    float* orow = out + (size_t)b * Dd;

    const int nc = min(g_cnt[b], CAP);
    if (nc == 0) {
        for (int i = tid; i < Dd; i += 256) orow[i] = 0.f;
        return;
    }

    __shared__ __align__(16) float qrow[Dd];
    __shared__ int   cidx[CAP];
    __shared__ float cex[CAP];
    __shared__ float cw[CAP];
    __shared__ int s_state, s_am, s_nf;

    {
        const float4* q4 = (const float4*)(query + (size_t)b * Dd);
        float4* d4 = (float4*)qrow;
        for (int i = tid; i < Dd / 4; i += 256) d4[i] = q4[i];
    }
    for (int i = tid; i < nc; i += 256) cidx[i] = g_cand[(size_t)b * CAP + i];
    __syncthreads();

    if (tid == 0) {          // sort ascending for determinism (nc is tiny)
        for (int i = 1; i < nc; i++) {
            int key = cidx[i], k2 = i - 1;
            while (k2 >= 0 && cidx[k2] > key) { cidx[k2 + 1] = cidx[k2]; k2--; }
            cidx[k2 + 1] = key;
        }
    }
    __syncthreads();

    const float qinv = g_qinv[b];
    const float4* q4 = (const float4*)qrow;
    for (int c = w; c < nc; c += 8) {     // one warp per candidate: exact fp32 dot
        const float4* s4 = (const float4*)(qset + (size_t)cidx[c] * Dd);
        float p = 0.f;
        for (int i = lane; i < Dd / 4; i += 32) {
            float4 a = q4[i], v = s4[i];
            p = fmaf(a.x, v.x, p); p = fmaf(a.y, v.y, p);
            p = fmaf(a.z, v.z, p); p = fmaf(a.w, v.w, p);
        }
        p = warp_sum(p);
        if (lane == 0) cex[c] = p * qinv * g_sinv[cidx[c]];
    }
    __syncthreads();

    if (tid == 0) {
        int cntE = 0; float sum = 0.f;
        for (int c = 0; c < nc; c++) if (cex[c] > 0.5f) { cntE++; sum += cex[c]; }
        if (cntE == 0) { s_state = 0; }
        else {
            const float fc = (float)cntE;
            const float mean = sum / fc;
            float var = 0.f;
            for (int c = 0; c < nc; c++)
                if (cex[c] > 0.5f) { float d = cex[c] - mean; var = fmaf(d, d, var); }
            var /= fc;
            const float dyn = mean - 0.5f * sqrtf(var);
            int fcnt = 0; float mx = -1e30f;
            for (int c = 0; c < nc; c++)
                if (cex[c] > 0.5f && cex[c] > dyn) { fcnt++; if (cex[c] > mx) mx = cex[c]; }
            if (fcnt == 0) {   // fallback 1: argmin |sim-mean| is provably a candidate
                float bv = 3.4e38f; int bi = 0;
                for (int c = 0; c < nc; c++) {
                    float dv = fabsf(cex[c] - mean);
                    if (dv < bv) { bv = dv; bi = cidx[c]; }
                }
                s_state = 1; s_am = bi;
            } else {
                float den = 0.f;
                for (int c = 0; c < nc; c++) {
                    if (cex[c] > 0.5f && cex[c] > dyn) { float e = __expf(cex[c] - mx); cw[c] = e; den += e; }
                    else cw[c] = 0.f;
                }
                const float inv = 1.0f / den;
                int nf = 0;
                for (int c = 0; c < nc; c++)
                    if (cw[c] > 0.f) { cidx[nf] = cidx[c]; cw[nf] = cw[c] * inv; nf++; }
                s_state = 2; s_nf = nf;
            }
        }
    }
    __syncthreads();

    float4* o4 = (float4*)orow;
    if (s_state == 0) {
        const float4 z = make_float4(0.f, 0.f, 0.f, 0.f);
        for (int i = tid; i < Dd / 4; i += 256) o4[i] = z;
    } else if (s_state == 1) {
        const float4* t4 = (const float4*)(tgt + (size_t)s_am * Dd);
        for (int i = tid; i < Dd / 4; i += 256) o4[i] = t4[i];
    } else {
        const int nf = s_nf;
        for (int i = tid; i < Dd / 4; i += 256) {
            float4 a = make_float4(0.f, 0.f, 0.f, 0.f);
            for (int c = 0; c < nf; c++) {
                const float4 t = *(const float4*)(tgt + (size_t)cidx[c] * Dd + i * 4);
                const float wgt = cw[c];
                a.x = fmaf(wgt, t.x, a.x); a.y = fmaf(wgt, t.y, a.y);
                a.z = fmaf(wgt, t.z, a.z); a.w = fmaf(wgt, t.w, a.w);
            }
            o4[i] = a;
        }
    }
}

// ---------------- launch (only harness pointers cross the host/device line) ----
extern "C" void kernel_launch(void* const* d_in, const int* in_sizes, int n_in,
                              void* d_out, int out_size) {
    const float* query      = (const float*)d_in[0];
    const float* query_set  = (const float*)d_in[1];
    const float* target_set = (const float*)d_in[2];
    float* out = (float*)d_out;

    normalize_all<<<Bq + Mm, 256>>>(query, query_set);

    cudaFuncSetAttribute(sims_gemm, cudaFuncAttributeMaxDynamicSharedMemorySize, DYN_SMEM);
    dim3 grid(Mm / BN, Bq / BM);
    sims_gemm<<<grid, 256, DYN_SMEM>>>();

    stats2<<<Bq, 256>>>(query, query_set, target_set, out);
}

// round 8
// speedup vs baseline: 2.1430x; 1.0344x over previous
#include <cuda_runtime.h>
#include <cuda_bf16.h>
#include <cuda_fp8.h>
#include <stdint.h>

#define Bq 2048
#define Mm 8192
#define Dd 2048
#define CAP 512

// ---- GEMM tiling (fp8: 128 elems per 128B k-row) ----
#define BM 128
#define BN 128
#define BKB 128                        // k-chunk in BYTES (= 128 fp8 elems)
#define NTK (Dd / BKB)                 // 16
#define A_SZ (BM * 128)                // bytes per stage
#define B_SZ (BN * 128)
#define STAGE (A_SZ + B_SZ)            // 32768
#define NSTAGE 3                       // 3 stages -> 97 KB -> 2 CTAs/SM
#define DYN_SMEM (NSTAGE * STAGE + 1024)

// ---------------- scratch (device globals, referenced in device code ONLY) ----
__device__ __align__(16) uint8_t g_qn8[(size_t)Bq * Dd];   // 4 MB  (e4m3)
__device__ __align__(16) uint8_t g_sn8[(size_t)Mm * Dd];   // 16 MB (e4m3)
__device__ float g_qinv[Bq];
__device__ float g_sinv[Mm];
__device__ int   g_cnt[Bq];
__device__ int   g_cand[(size_t)Bq * CAP];

// ---------------- helpers ----------------
__device__ __forceinline__ uint32_t smem_u32(const void* p) {
    uint32_t a;
    asm("{ .reg .u64 t; cvta.to.shared.u64 t, %1; cvt.u32.u64 %0, t; }" : "=r"(a) : "l"(p));
    return a;
}
#define SW128(o) ((o) ^ (((o) >> 3) & 0x70))

__device__ __forceinline__ void cp_async16(uint32_t dst, const void* src) {
    asm volatile("cp.async.cg.shared.global [%0], [%1], 16;" :: "r"(dst), "l"(src) : "memory");
}
#define CP_COMMIT() asm volatile("cp.async.commit_group;" ::: "memory")
#define CP_WAIT(n)  asm volatile("cp.async.wait_group %0;" :: "n"(n) : "memory")

__device__ __forceinline__ void ldsm_x4(uint32_t* r, uint32_t addr) {
    asm volatile("ldmatrix.sync.aligned.m8n8.x4.shared.b16 {%0,%1,%2,%3}, [%4];"
                 : "=r"(r[0]), "=r"(r[1]), "=r"(r[2]), "=r"(r[3]) : "r"(addr));
}
// fp8 e4m3 MMA: fragment byte-layout identical to m16n8k16 bf16
__device__ __forceinline__ void mma_fp8(float* d, const uint32_t* a, const uint32_t* b) {
    asm volatile(
        "mma.sync.aligned.m16n8k32.row.col.f32.e4m3.e4m3.f32 "
        "{%0,%1,%2,%3}, {%4,%5,%6,%7}, {%8,%9}, {%0,%1,%2,%3};\n"
        : "+f"(d[0]), "+f"(d[1]), "+f"(d[2]), "+f"(d[3])
        : "r"(a[0]), "r"(a[1]), "r"(a[2]), "r"(a[3]), "r"(b[0]), "r"(b[1]));
}
__device__ __forceinline__ float warp_sum(float v) {
#pragma unroll
    for (int o = 16; o; o >>= 1) v += __shfl_xor_sync(0xffffffffu, v, o);
    return v;
}

// ---------------- kernel 1: merged row norms + e4m3 normalized copy ----------------
__global__ __launch_bounds__(256) void normalize_all(const float* __restrict__ q,
                                                     const float* __restrict__ s) {
    const int b = blockIdx.x;
    const float* r;
    uint8_t* db;
    float* dinv_slot;
    if (b < Bq) {
        if (threadIdx.x == 0) g_cnt[b] = 0;    // reset per launch
        r = q + (size_t)b * Dd; db = g_qn8 + (size_t)b * Dd; dinv_slot = &g_qinv[b];
    } else {
        const int m = b - Bq;
        r = s + (size_t)m * Dd; db = g_sn8 + (size_t)m * Dd; dinv_slot = &g_sinv[m];
    }
    const float4* r4 = (const float4*)r;
    float4 v[2];
    float ss = 0.f;
#pragma unroll
    for (int k = 0; k < 2; k++) {
        v[k] = r4[threadIdx.x + k * 256];
        ss = fmaf(v[k].x, v[k].x, ss); ss = fmaf(v[k].y, v[k].y, ss);
        ss = fmaf(v[k].z, v[k].z, ss); ss = fmaf(v[k].w, v[k].w, ss);
    }
    __shared__ float red[8];
    int lane = threadIdx.x & 31, w = threadIdx.x >> 5;
    ss = warp_sum(ss);
    if (lane == 0) red[w] = ss;
    __syncthreads();
    if (w == 0) {
        float t = (lane < 8) ? red[lane] : 0.f;
        t = warp_sum(t);
        if (lane == 0) red[0] = 1.0f / fmaxf(sqrtf(t), 1e-8f);
    }
    __syncthreads();
    const float inv = red[0];
    if (threadIdx.x == 0) *dinv_slot = inv;
    uint32_t* d32 = (uint32_t*)db;
#pragma unroll
    for (int k = 0; k < 2; k++) {
        float4 n = make_float4(v[k].x * inv, v[k].y * inv, v[k].z * inv, v[k].w * inv);
        __nv_fp8x4_e4m3 p(n);
        d32[threadIdx.x + k * 256] = *(uint32_t*)&p;
    }
}

// ---------------- kernel 2: cp.async + ldmatrix + fp8 mma.sync GEMM (2 CTAs/SM) ----
__global__ __launch_bounds__(256, 2) void sims_gemm() {
    extern __shared__ __align__(16) char dyn[];
    const int tid = threadIdx.x;
    const int lane = tid & 31;
    const int wid = tid >> 5;
    const int wm = wid >> 2;     // 0..1 : 64 rows
    const int wn = wid & 3;      // 0..3 : 32 cols

    // 1024-align dynamic smem
    const uint32_t draw = smem_u32(dyn);
    const uint32_t pad = (1024u - (draw & 1023u)) & 1023u;
    const uint32_t sm0 = draw + pad;

    const int bm0 = blockIdx.y * BM;
    const int bn0 = blockIdx.x * BN;

    // ---- cp.async fill mapping (byte-based) ----
    const int j = tid & 7;       // 16B chunk in 128B row
    const int r = tid >> 3;      // 0..31
    uint32_t sw[4];
#pragma unroll
    for (int i = 0; i < 4; i++) sw[i] = SW128((uint32_t)((r + 32 * i) * 128 + j * 16));
    const uint8_t* Ag = g_qn8 + (size_t)(bm0 + r) * Dd + j * 16;
    const uint8_t* Bg = g_sn8 + (size_t)(bn0 + r) * Dd + j * 16;

    // ---- ldmatrix address precompute ----
    const int sub = lane & 7;
    const uint32_t xr = (uint32_t)sub << 4;
    const uint32_t offA = ((lane >> 4) & 1) * 16;       // k-half select (16B)
    const int rowA_off = ((lane >> 3) & 1) * 8 + sub;   // row +0/+8
    uint32_t aRow[4];
#pragma unroll
    for (int mi = 0; mi < 4; mi++)
        aRow[mi] = sm0 + (uint32_t)(wm * 64 + mi * 16 + rowA_off) * 128;
    const uint32_t offB = ((lane >> 3) & 1) * 16;
    const int rowB_off = ((lane >> 4) & 1) * 8 + sub;
    uint32_t bRow[2];
#pragma unroll
    for (int nj = 0; nj < 2; nj++)
        bRow[nj] = sm0 + A_SZ + (uint32_t)(wn * 32 + nj * 16 + rowB_off) * 128;

    float acc[4][4][4];
#pragma unroll
    for (int mi = 0; mi < 4; mi++)
#pragma unroll
        for (int ni = 0; ni < 4; ni++)
#pragma unroll
            for (int k = 0; k < 4; k++) acc[mi][ni][k] = 0.f;

    // ---- prologue: issue first NSTAGE-1 = 2 stages ----
#pragma unroll
    for (int s = 0; s < NSTAGE - 1; s++) {
        const uint32_t st = sm0 + s * STAGE;
        const uint8_t* ak = Ag + (size_t)s * BKB;
        const uint8_t* bk = Bg + (size_t)s * BKB;
#pragma unroll
        for (int i = 0; i < 4; i++) cp_async16(st + sw[i], ak + (size_t)(32 * i) * Dd);
#pragma unroll
        for (int i = 0; i < 4; i++) cp_async16(st + A_SZ + sw[i], bk + (size_t)(32 * i) * Dd);
        CP_COMMIT();
    }

    int s_cur = 0, s_nxt = NSTAGE - 1;   // rotating slot indices (avoid % in loop)
    for (int kt = 0; kt < NTK; kt++) {
        CP_WAIT(NSTAGE - 2);      // this thread's stage-kt copies done
        __syncthreads();          // -> all threads' copies visible

        // issue stage kt+2 into slot s_nxt (its prior readers: tile kt-1, done)
        if (kt + NSTAGE - 1 < NTK) {
            const uint32_t st = sm0 + s_nxt * STAGE;
            const uint8_t* ak = Ag + (size_t)(kt + NSTAGE - 1) * BKB;
            const uint8_t* bk = Bg + (size_t)(kt + NSTAGE - 1) * BKB;
#pragma unroll
            for (int i = 0; i < 4; i++) cp_async16(st + sw[i], ak + (size_t)(32 * i) * Dd);
#pragma unroll
            for (int i = 0; i < 4; i++) cp_async16(st + A_SZ + sw[i], bk + (size_t)(32 * i) * Dd);
        }
        CP_COMMIT();

        // compute stage kt from slot s_cur
        const uint32_t sbase = (uint32_t)(s_cur * STAGE);
#pragma unroll
        for (int ks = 0; ks < 4; ks++) {
            const uint32_t kpA = (((uint32_t)ks * 32 + offA) ^ xr) + sbase;
            const uint32_t kpB = (((uint32_t)ks * 32 + offB) ^ xr) + sbase;
            uint32_t af[4][4], bfr[2][4];
#pragma unroll
            for (int mi = 0; mi < 4; mi++) ldsm_x4(af[mi], aRow[mi] + kpA);
#pragma unroll
            for (int nj = 0; nj < 2; nj++) ldsm_x4(bfr[nj], bRow[nj] + kpB);
#pragma unroll
            for (int mi = 0; mi < 4; mi++)
#pragma unroll
                for (int ni = 0; ni < 4; ni++)
                    mma_fp8(acc[mi][ni], af[mi], &bfr[ni >> 1][(ni & 1) * 2]);
        }

        s_cur = (s_cur == NSTAGE - 1) ? 0 : s_cur + 1;
        s_nxt = (s_nxt == NSTAGE - 1) ? 0 : s_nxt + 1;
    }

    // ---- epilogue: candidate push straight from registers ----
    const int g = lane >> 2, tk = lane & 3;
#pragma unroll
    for (int mi = 0; mi < 4; mi++) {
#pragma unroll
        for (int ni = 0; ni < 4; ni++) {
#pragma unroll
            for (int k = 0; k < 4; k++) {
                const float v = acc[mi][ni][k];
                if (v > 0.45f) {
                    const int row = bm0 + wm * 64 + mi * 16 + g + (k >> 1) * 8;
                    const int col = bn0 + wn * 32 + ni * 8 + tk * 2 + (k & 1);
                    const int pos = atomicAdd(&g_cnt[row], 1);
                    if (pos < CAP) g_cand[(size_t)row * CAP + pos] = col;
                }
            }
        }
    }
}

// ---------------- kernel 3: exact stats + softmax gather (vectorized) ----------------
__global__ __launch_bounds__(256) void stats2(const float* __restrict__ query,
                                              const float* __restrict__ qset,
                                              const float* __restrict__ tgt,
                                              float* __restrict__ out) {
    const int b = blockIdx.x;
    const int tid = threadIdx.x, lane = tid & 31, w = tid >> 5;
    float* orow = out + (size_t)b * Dd;

    const int nc = min(g_cnt[b], CAP);
    if (nc == 0) {
        for (int i = tid; i < Dd; i += 256) orow[i] = 0.f;
        return;
    }

    __shared__ __align__(16) float qrow[Dd];
    __shared__ int   cidx[CAP];
    __shared__ float cex[CAP];
    __shared__ float cw[CAP];
    __shared__ int s_state, s_am, s_nf;

    {
        const float4* q4 = (const float4*)(query + (size_t)b * Dd);
        float4* d4 = (float4*)qrow;
        for (int i = tid; i < Dd / 4; i += 256) d4[i] = q4[i];
    }
    for (int i = tid; i < nc; i += 256) cidx[i] = g_cand[(size_t)b * CAP + i];
    __syncthreads();

    if (tid == 0) {          // sort ascending for determinism (nc is tiny)
        for (int i = 1; i < nc; i++) {
            int key = cidx[i], k2 = i - 1;
            while (k2 >= 0 && cidx[k2] > key) { cidx[k2 + 1] = cidx[k2]; k2--; }
            cidx[k2 + 1] = key;
        }
    }
    __syncthreads();

    const float qinv = g_qinv[b];
    const float4* q4 = (const float4*)qrow;
    for (int c = w; c < nc; c += 8) {     // one warp per candidate: exact fp32 dot
        const float4* s4 = (const float4*)(qset + (size_t)cidx[c] * Dd);
        float p = 0.f;
        for (int i = lane; i < Dd / 4; i += 32) {
            float4 a = q4[i], v = s4[i];
            p = fmaf(a.x, v.x, p); p = fmaf(a.y, v.y, p);
            p = fmaf(a.z, v.z, p); p = fmaf(a.w, v.w, p);
        }
        p = warp_sum(p);
        if (lane == 0) cex[c] = p * qinv * g_sinv[cidx[c]];
    }
    __syncthreads();

    if (tid == 0) {
        int cntE = 0; float sum = 0.f;
        for (int c = 0; c < nc; c++) if (cex[c] > 0.5f) { cntE++; sum += cex[c]; }
        if (cntE == 0) { s_state = 0; }
        else {
            const float fc = (float)cntE;
            const float mean = sum / fc;
            float var = 0.f;
            for (int c = 0; c < nc; c++)
                if (cex[c] > 0.5f) { float d = cex[c] - mean; var = fmaf(d, d, var); }
            var /= fc;
            const float dyn = mean - 0.5f * sqrtf(var);
            int fcnt = 0; float mx = -1e30f;
            for (int c = 0; c < nc; c++)
                if (cex[c] > 0.5f && cex[c] > dyn) { fcnt++; if (cex[c] > mx) mx = cex[c]; }
            if (fcnt == 0) {   // fallback 1: argmin |sim-mean| is provably a candidate
                float bv = 3.4e38f; int bi = 0;
                for (int c = 0; c < nc; c++) {
                    float dv = fabsf(cex[c] - mean);
                    if (dv < bv) { bv = dv; bi = cidx[c]; }
                }
                s_state = 1; s_am = bi;
            } else {
                float den = 0.f;
                for (int c = 0; c < nc; c++) {
                    if (cex[c] > 0.5f && cex[c] > dyn) { float e = __expf(cex[c] - mx); cw[c] = e; den += e; }
                    else cw[c] = 0.f;
                }
                const float inv = 1.0f / den;
                int nf = 0;
                for (int c = 0; c < nc; c++)
                    if (cw[c] > 0.f) { cidx[nf] = cidx[c]; cw[nf] = cw[c] * inv; nf++; }
                s_state = 2; s_nf = nf;
            }
        }
    }
    __syncthreads();

    float4* o4 = (float4*)orow;
    if (s_state == 0) {
        const float4 z = make_float4(0.f, 0.f, 0.f, 0.f);
        for (int i = tid; i < Dd / 4; i += 256) o4[i] = z;
    } else if (s_state == 1) {
        const float4* t4 = (const float4*)(tgt + (size_t)s_am * Dd);
        for (int i = tid; i < Dd / 4; i += 256) o4[i] = t4[i];
    } else {
        const int nf = s_nf;
        for (int i = tid; i < Dd / 4; i += 256) {
            float4 a = make_float4(0.f, 0.f, 0.f, 0.f);
            for (int c = 0; c < nf; c++) {
                const float4 t = *(const float4*)(tgt + (size_t)cidx[c] * Dd + i * 4);
                const float wgt = cw[c];
                a.x = fmaf(wgt, t.x, a.x); a.y = fmaf(wgt, t.y, a.y);
                a.z = fmaf(wgt, t.z, a.z); a.w = fmaf(wgt, t.w, a.w);
            }
            o4[i] = a;
        }
    }
}

// ---------------- launch (only harness pointers cross the host/device line) ----
extern "C" void kernel_launch(void* const* d_in, const int* in_sizes, int n_in,
                              void* d_out, int out_size) {
    const float* query      = (const float*)d_in[0];
    const float* query_set  = (const float*)d_in[1];
    const float* target_set = (const float*)d_in[2];
    float* out = (float*)d_out;

    normalize_all<<<Bq + Mm, 256>>>(query, query_set);

    cudaFuncSetAttribute(sims_gemm, cudaFuncAttributeMaxDynamicSharedMemorySize, DYN_SMEM);
    dim3 grid(Mm / BN, Bq / BM);
    sims_gemm<<<grid, 256, DYN_SMEM>>>();

    stats2<<<Bq, 256>>>(query, query_set, target_set, out);
}